// round 1
// baseline (speedup 1.0000x reference)
#include <cuda_runtime.h>

// CrimeModelLSTM: 2-layer LSTM (H=8), B=4096, T=512, input dim 1, FC head [4,8].
// Layout: 8 threads per batch element; thread j owns hidden unit j and gate rows
// {j, 8+j, 16+j, 24+j}. All weights live in registers (scaled so activations are
// EX2+RCP only). h broadcast within the 8-lane group via __shfl_sync.

#define LOG2E_F 1.4426950408889634f

__device__ __forceinline__ float ex2f(float x) {
    float r; asm("ex2.approx.f32 %0, %1;" : "=f"(r) : "f"(x)); return r;
}
__device__ __forceinline__ float rcpf(float x) {
    float r; asm("rcp.approx.f32 %0, %1;" : "=f"(r) : "f"(x)); return r;
}
// pre-activation already scaled by -log2(e):  sigmoid(x) = 1/(1+2^(-x*log2e))
__device__ __forceinline__ float sig_s(float p) {
    return rcpf(1.0f + ex2f(p));
}
// pre-activation already scaled by -2*log2(e): tanh(x) = 2/(1+2^(-2x*log2e)) - 1
__device__ __forceinline__ float tanh_s(float p) {
    return fmaf(rcpf(1.0f + ex2f(p)), 2.0f, -1.0f);
}

__global__ void __launch_bounds__(32)
lstm2_kernel(const float* __restrict__ x,
             const float* __restrict__ Wih1, const float* __restrict__ Whh1,
             const float* __restrict__ bih1, const float* __restrict__ bhh1,
             const float* __restrict__ Wih2, const float* __restrict__ Whh2,
             const float* __restrict__ bih2, const float* __restrict__ bhh2,
             const float* __restrict__ Wfc,  const float* __restrict__ bfc,
             float* __restrict__ out)
{
    constexpr int T = 512;
    constexpr int H = 8;

    const int tid  = blockIdx.x * 32 + threadIdx.x;
    const int e    = tid >> 3;          // batch element
    const int j    = tid & 7;           // hidden unit owned by this thread
    const int base = threadIdx.x & 24;  // first lane of this 8-lane group

    // gate scales (order i, f, g, o): sigmoid rows get -log2e, cell gate -2log2e
    float scale[4];
    scale[0] = -LOG2E_F; scale[1] = -LOG2E_F;
    scale[2] = -2.0f * LOG2E_F; scale[3] = -LOG2E_F;

    // ---- load + pre-scale weights into registers (loop-invariant) ----
    float wh1[4][H], wi2[4][H], wh2[4][H];
    float wx1[4], bb1[4], bb2[4];
    #pragma unroll
    for (int g = 0; g < 4; g++) {
        const int row = g * 8 + j;
        const float s = scale[g];
        wx1[g] = Wih1[row] * s;
        bb1[g] = (bih1[row] + bhh1[row]) * s;
        bb2[g] = (bih2[row] + bhh2[row]) * s;
        #pragma unroll
        for (int k = 0; k < H; k++) {
            wh1[g][k] = Whh1[row * H + k] * s;
            wi2[g][k] = Wih2[row * H + k] * s;
            wh2[g][k] = Whh2[row * H + k] * s;
        }
    }
    const float c2t = -2.0f * LOG2E_F;  // scale for tanh(c)

    // ---- state ----
    float h1[H], h2[H];
    #pragma unroll
    for (int k = 0; k < H; k++) { h1[k] = 0.0f; h2[k] = 0.0f; }
    float c1 = 0.0f, c2 = 0.0f;

    const float4* __restrict__ xp = reinterpret_cast<const float4*>(x + (long)e * T);
    float4 xv = xp[0];

    for (int tt = 0; tt < T / 4; ++tt) {
        // prefetch next 4 timesteps of x (uniform index, no branch)
        const int nxt = (tt + 1 < T / 4) ? (tt + 1) : tt;
        float4 xn = xp[nxt];

        float xs[4] = {xv.x, xv.y, xv.z, xv.w};

        #pragma unroll
        for (int q = 0; q < 4; q++) {
            const float xt = xs[q];

            // ---------- layer 1 ----------
            float p[4];
            #pragma unroll
            for (int g = 0; g < 4; g++) p[g] = fmaf(wx1[g], xt, bb1[g]);
            #pragma unroll
            for (int k = 0; k < H; k++) {
                const float hk = h1[k];
                #pragma unroll
                for (int g = 0; g < 4; g++) p[g] = fmaf(wh1[g][k], hk, p[g]);
            }
            {
                const float gi = sig_s(p[0]);
                const float gf = sig_s(p[1]);
                const float gg = tanh_s(p[2]);
                const float go = sig_s(p[3]);
                c1 = fmaf(gf, c1, gi * gg);
                const float th = tanh_s(c1 * c2t);
                const float h1own = go * th;
                #pragma unroll
                for (int k = 0; k < H; k++)
                    h1[k] = __shfl_sync(0xffffffffu, h1own, base + k);
            }

            // ---------- layer 2 ----------
            #pragma unroll
            for (int g = 0; g < 4; g++) p[g] = bb2[g];
            #pragma unroll
            for (int k = 0; k < H; k++) {
                const float hk = h1[k];
                #pragma unroll
                for (int g = 0; g < 4; g++) p[g] = fmaf(wi2[g][k], hk, p[g]);
            }
            #pragma unroll
            for (int k = 0; k < H; k++) {
                const float hk = h2[k];
                #pragma unroll
                for (int g = 0; g < 4; g++) p[g] = fmaf(wh2[g][k], hk, p[g]);
            }
            {
                const float gi = sig_s(p[0]);
                const float gf = sig_s(p[1]);
                const float gg = tanh_s(p[2]);
                const float go = sig_s(p[3]);
                c2 = fmaf(gf, c2, gi * gg);
                const float th = tanh_s(c2 * c2t);
                const float h2own = go * th;
                #pragma unroll
                for (int k = 0; k < H; k++)
                    h2[k] = __shfl_sync(0xffffffffu, h2own, base + k);
            }
        }
        xv = xn;
    }

    // ---- FC head: out[e][j] = b_fc[j] + sum_k Wfc[j][k] * h2[k], j < 4 ----
    if (j < 4) {
        float acc = bfc[j];
        #pragma unroll
        for (int k = 0; k < H; k++) acc = fmaf(Wfc[j * H + k], h2[k], acc);
        out[e * 4 + j] = acc;
    }
}

extern "C" void kernel_launch(void* const* d_in, const int* in_sizes, int n_in,
                              void* d_out, int out_size)
{
    const float* x    = (const float*)d_in[0];
    const float* Wih1 = (const float*)d_in[1];
    const float* Whh1 = (const float*)d_in[2];
    const float* bih1 = (const float*)d_in[3];
    const float* bhh1 = (const float*)d_in[4];
    const float* Wih2 = (const float*)d_in[5];
    const float* Whh2 = (const float*)d_in[6];
    const float* bih2 = (const float*)d_in[7];
    const float* bhh2 = (const float*)d_in[8];
    const float* Wfc  = (const float*)d_in[9];
    const float* bfc  = (const float*)d_in[10];
    float* out = (float*)d_out;

    const int B = 4096;
    // 8 threads per element, 32-thread CTAs -> 1024 CTAs (near-perfect wave balance)
    dim3 grid(B * 8 / 32), block(32);
    lstm2_kernel<<<grid, block>>>(x, Wih1, Whh1, bih1, bhh1,
                                  Wih2, Whh2, bih2, bhh2, Wfc, bfc, out);
}

// round 2
// speedup vs baseline: 1.0750x; 1.0750x over previous
#include <cuda_runtime.h>

// CrimeModelLSTM: 2-layer LSTM (H=8), B=4096, T=512, input dim 1, FC head [4,8].
// 8 threads per element; thread j owns hidden unit j (gate rows j,8+j,16+j,24+j).
// Weights in registers, activations via EX2+RCP (scales folded into weights).
// SOFTWARE-PIPELINED across layers: body computes L2(t) and L1(t+1) together —
// the two recurrent chains run in parallel, halving the per-step critical path.

#define LOG2E_F 1.4426950408889634f

__device__ __forceinline__ float ex2f(float x) {
    float r; asm("ex2.approx.f32 %0, %1;" : "=f"(r) : "f"(x)); return r;
}
__device__ __forceinline__ float rcpf(float x) {
    float r; asm("rcp.approx.f32 %0, %1;" : "=f"(r) : "f"(x)); return r;
}
// pre-activation scaled by -log2e:  sigmoid(x) = 1/(1+2^(-x*log2e))
__device__ __forceinline__ float sig_s(float p)  { return rcpf(1.0f + ex2f(p)); }
// pre-activation scaled by -2*log2e: tanh(x) = 2/(1+2^(-2x*log2e)) - 1
__device__ __forceinline__ float tanh_s(float p) { return fmaf(rcpf(1.0f + ex2f(p)), 2.0f, -1.0f); }

__global__ void __launch_bounds__(32)
lstm2_kernel(const float* __restrict__ x,
             const float* __restrict__ Wih1, const float* __restrict__ Whh1,
             const float* __restrict__ bih1, const float* __restrict__ bhh1,
             const float* __restrict__ Wih2, const float* __restrict__ Whh2,
             const float* __restrict__ bih2, const float* __restrict__ bhh2,
             const float* __restrict__ Wfc,  const float* __restrict__ bfc,
             float* __restrict__ out)
{
    constexpr int T = 512;
    constexpr int H = 8;

    const int tid = blockIdx.x * 32 + threadIdx.x;
    const int e   = tid >> 3;   // batch element
    const int j   = tid & 7;    // hidden unit owned by this thread

    float scale[4];
    scale[0] = -LOG2E_F; scale[1] = -LOG2E_F;
    scale[2] = -2.0f * LOG2E_F; scale[3] = -LOG2E_F;
    const float c2t = -2.0f * LOG2E_F;   // scale for tanh(c)

    // ---- weights in registers, pre-scaled ----
    float wh1[4][H], wi2[4][H], wh2[4][H];
    float wx1[4], bb1[4], bb2[4];
    #pragma unroll
    for (int g = 0; g < 4; g++) {
        const int row = g * 8 + j;
        const float s = scale[g];
        wx1[g] = Wih1[row] * s;
        bb1[g] = (bih1[row] + bhh1[row]) * s;
        bb2[g] = (bih2[row] + bhh2[row]) * s;
        #pragma unroll
        for (int k = 0; k < H; k++) {
            wh1[g][k] = Whh1[row * H + k] * s;
            wi2[g][k] = Wih2[row * H + k] * s;
            wh2[g][k] = Whh2[row * H + k] * s;
        }
    }

    // ---- state ----
    float h1[H], h2[H];
    #pragma unroll
    for (int k = 0; k < H; k++) { h1[k] = 0.0f; h2[k] = 0.0f; }
    float c1 = 0.0f, c2 = 0.0f;

    const float4* __restrict__ xp = reinterpret_cast<const float4*>(x + (long)e * T);
    float4 xv = xp[0];

    // ---- prologue: L1 step 0 (h1 = 0, so only x term) ----
    {
        float p[4];
        #pragma unroll
        for (int g = 0; g < 4; g++) p[g] = fmaf(wx1[g], xv.x, bb1[g]);
        const float gi = sig_s(p[0]);
        const float gf = sig_s(p[1]);
        const float gg = tanh_s(p[2]);
        const float go = sig_s(p[3]);
        c1 = fmaf(gf, c1, gi * gg);
        const float h1own = go * tanh_s(c1 * c2t);
        #pragma unroll
        for (int k = 0; k < H; k++)
            h1[k] = __shfl_sync(0xffffffffu, h1own, k, 8);
    }

    // ---- main loop: body computes L2(t) and L1(t+1); both use h1(t) ----
    for (int tt = 0; tt < T / 4; ++tt) {
        const int nxt = (tt + 1 < T / 4) ? (tt + 1) : tt;
        float4 xn = xp[nxt];
        // x values for L1 steps t+1 at q=0..3 within this chunk
        float xs[4] = {xv.y, xv.z, xv.w, xn.x};

        #pragma unroll
        for (int q = 0; q < 4; q++) {
            // -- gate pre-activations: L2(t) from (h1, h2), L1(t+1) from (x, h1)
            //    (independent of each other; ptxas interleaves both FMA blocks)
            float p2[4], p1[4];
            #pragma unroll
            for (int g = 0; g < 4; g++) p2[g] = bb2[g];
            #pragma unroll
            for (int g = 0; g < 4; g++) p1[g] = fmaf(wx1[g], xs[q], bb1[g]);
            #pragma unroll
            for (int k = 0; k < H; k++) {
                const float hk = h1[k];
                #pragma unroll
                for (int g = 0; g < 4; g++) p2[g] = fmaf(wi2[g][k], hk, p2[g]);
                #pragma unroll
                for (int g = 0; g < 4; g++) p1[g] = fmaf(wh1[g][k], hk, p1[g]);
            }
            #pragma unroll
            for (int k = 0; k < H; k++) {
                const float hk = h2[k];
                #pragma unroll
                for (int g = 0; g < 4; g++) p2[g] = fmaf(wh2[g][k], hk, p2[g]);
            }

            // -- L1(t+1) activation chain → new h1
            const float i1 = sig_s(p1[0]);
            const float f1 = sig_s(p1[1]);
            const float g1 = tanh_s(p1[2]);
            const float o1 = sig_s(p1[3]);
            // -- L2(t) activation chain → h2
            const float i2 = sig_s(p2[0]);
            const float f2 = sig_s(p2[1]);
            const float g2 = tanh_s(p2[2]);
            const float o2 = sig_s(p2[3]);

            c1 = fmaf(f1, c1, i1 * g1);
            c2 = fmaf(f2, c2, i2 * g2);
            const float h1own = o1 * tanh_s(c1 * c2t);
            const float h2own = o2 * tanh_s(c2 * c2t);

            float h1n[H];
            #pragma unroll
            for (int k = 0; k < H; k++) {
                h1n[k]  = __shfl_sync(0xffffffffu, h1own, k, 8);
                h2[k]   = __shfl_sync(0xffffffffu, h2own, k, 8);
            }
            #pragma unroll
            for (int k = 0; k < H; k++) h1[k] = h1n[k];
        }
        xv = xn;
    }
    // NOTE: loop computed L2 for steps 0..T-1 (last body iteration's L1(T) is
    // computed with a clamped x and its result is simply unused). h2 = h2(T-1).

    // ---- FC head ----
    if (j < 4) {
        float acc = bfc[j];
        #pragma unroll
        for (int k = 0; k < H; k++) acc = fmaf(Wfc[j * H + k], h2[k], acc);
        out[e * 4 + j] = acc;
    }
}

extern "C" void kernel_launch(void* const* d_in, const int* in_sizes, int n_in,
                              void* d_out, int out_size)
{
    const float* x    = (const float*)d_in[0];
    const float* Wih1 = (const float*)d_in[1];
    const float* Whh1 = (const float*)d_in[2];
    const float* bih1 = (const float*)d_in[3];
    const float* bhh1 = (const float*)d_in[4];
    const float* Wih2 = (const float*)d_in[5];
    const float* Whh2 = (const float*)d_in[6];
    const float* bih2 = (const float*)d_in[7];
    const float* bhh2 = (const float*)d_in[8];
    const float* Wfc  = (const float*)d_in[9];
    const float* bfc  = (const float*)d_in[10];
    float* out = (float*)d_out;

    const int B = 4096;
    dim3 grid(B * 8 / 32), block(32);
    lstm2_kernel<<<grid, block>>>(x, Wih1, Whh1, bih1, bhh1,
                                  Wih2, Whh2, bih2, bhh2, Wfc, bfc, out);
}

// round 3
// speedup vs baseline: 1.5605x; 1.4517x over previous
#include <cuda_runtime.h>

// CrimeModelLSTM: 2-layer LSTM (H=8), B=4096, T=512, FC head [4,8].
// 8 threads/element; thread j owns hidden unit j (gate rows j,8+j,16+j,24+j).
// R3: packed fma.rn.f32x2 for all gate FMAs (gate pairs (i,f),(g,o)),
//     tanh.approx-based activations (1 MUFU each; sigmoid = .5+.5*tanh(x/2),
//     the 1/2 folded into weights). Cross-layer software pipelining kept.

typedef unsigned long long u64;

__device__ __forceinline__ u64 pk2(float lo, float hi) {
    u64 r; asm("mov.b64 %0, {%1,%2};" : "=l"(r) : "f"(lo), "f"(hi)); return r;
}
__device__ __forceinline__ void upk(u64 v, float& lo, float& hi) {
    asm("mov.b64 {%0,%1}, %2;" : "=f"(lo), "=f"(hi) : "l"(v));
}
__device__ __forceinline__ u64 fma2(u64 a, u64 b, u64 c) {
    u64 d; asm("fma.rn.f32x2 %0, %1, %2, %3;" : "=l"(d) : "l"(a), "l"(b), "l"(c)); return d;
}
__device__ __forceinline__ float tanhap(float x) {
    float r; asm("tanh.approx.f32 %0, %1;" : "=f"(r) : "f"(x)); return r;
}
// input pre-scaled by 0.5: sigmoid(2p) = 0.5 + 0.5*tanh(p)
__device__ __forceinline__ float sig_h(float p) { return fmaf(tanhap(p), 0.5f, 0.5f); }

__global__ void __launch_bounds__(32)
lstm2_kernel(const float* __restrict__ x,
             const float* __restrict__ Wih1, const float* __restrict__ Whh1,
             const float* __restrict__ bih1, const float* __restrict__ bhh1,
             const float* __restrict__ Wih2, const float* __restrict__ Whh2,
             const float* __restrict__ bih2, const float* __restrict__ bhh2,
             const float* __restrict__ Wfc,  const float* __restrict__ bfc,
             float* __restrict__ out)
{
    constexpr int T = 512;
    constexpr int H = 8;

    const int tid = blockIdx.x * 32 + threadIdx.x;
    const int e   = tid >> 3;   // batch element
    const int j   = tid & 7;    // hidden unit owned by this thread

    // per-gate scales: sigmoid rows (i,f,o) get 0.5 folded in; tanh row (g) 1.0
    const float gsc[4] = {0.5f, 0.5f, 1.0f, 0.5f};

    // ---- weights packed as gate pairs: pair0 = (i,f), pair1 = (g,o) ----
    u64 wh1p[2][H], wi2p[2][H], wh2p[2][H];
    u64 wx1p[2], bb1p[2], bb2p[2];
    #pragma unroll
    for (int p = 0; p < 2; p++) {
        const int gA = 2 * p, gB = 2 * p + 1;
        const int rA = gA * 8 + j, rB = gB * 8 + j;
        const float sA = gsc[gA], sB = gsc[gB];
        wx1p[p] = pk2(Wih1[rA] * sA, Wih1[rB] * sB);
        bb1p[p] = pk2((bih1[rA] + bhh1[rA]) * sA, (bih1[rB] + bhh1[rB]) * sB);
        bb2p[p] = pk2((bih2[rA] + bhh2[rA]) * sA, (bih2[rB] + bhh2[rB]) * sB);
        #pragma unroll
        for (int k = 0; k < H; k++) {
            wh1p[p][k] = pk2(Whh1[rA * H + k] * sA, Whh1[rB * H + k] * sB);
            wi2p[p][k] = pk2(Wih2[rA * H + k] * sA, Wih2[rB * H + k] * sB);
            wh2p[p][k] = pk2(Whh2[rA * H + k] * sA, Whh2[rB * H + k] * sB);
        }
    }

    // ---- state: h kept duplicated-packed (h,h) for FFMA2 operands ----
    u64 h1p[H], h2p[H];
    #pragma unroll
    for (int k = 0; k < H; k++) { h1p[k] = 0ull; h2p[k] = 0ull; }
    float c1 = 0.0f, c2 = 0.0f;

    const float4* __restrict__ xp = reinterpret_cast<const float4*>(x + (long)e * T);
    float4 xv = xp[0];

    // ---- prologue: L1 step 0 (h1 = 0: only x term) ----
    {
        u64 x2 = pk2(xv.x, xv.x);
        u64 P0 = fma2(wx1p[0], x2, bb1p[0]);
        u64 P1 = fma2(wx1p[1], x2, bb1p[1]);
        float a, b;
        upk(P0, a, b); const float i1 = sig_h(a), f1 = sig_h(b);
        upk(P1, a, b); const float g1 = tanhap(a), o1 = sig_h(b);
        c1 = fmaf(f1, c1, i1 * g1);
        const float h1o = o1 * tanhap(c1);
        #pragma unroll
        for (int k = 0; k < H; k++) {
            const float v = __shfl_sync(0xffffffffu, h1o, k, 8);
            h1p[k] = pk2(v, v);
        }
    }

    // ---- main loop: body computes L2(t) and L1(t+1); both consume h1(t) ----
    for (int tt = 0; tt < T / 4; ++tt) {
        const int nxt = (tt + 1 < T / 4) ? (tt + 1) : tt;
        float4 xn = xp[nxt];
        float xs[4] = {xv.y, xv.z, xv.w, xn.x};  // x for L1 step t+1

        #pragma unroll
        for (int q = 0; q < 4; q++) {
            u64 x2 = pk2(xs[q], xs[q]);
            u64 P1_0 = fma2(wx1p[0], x2, bb1p[0]);
            u64 P1_1 = fma2(wx1p[1], x2, bb1p[1]);
            u64 P2_0 = bb2p[0];
            u64 P2_1 = bb2p[1];
            #pragma unroll
            for (int k = 0; k < H; k++) {
                const u64 h = h1p[k];
                P2_0 = fma2(wi2p[0][k], h, P2_0);
                P2_1 = fma2(wi2p[1][k], h, P2_1);
                P1_0 = fma2(wh1p[0][k], h, P1_0);
                P1_1 = fma2(wh1p[1][k], h, P1_1);
            }
            #pragma unroll
            for (int k = 0; k < H; k++) {
                const u64 h = h2p[k];
                P2_0 = fma2(wh2p[0][k], h, P2_0);
                P2_1 = fma2(wh2p[1][k], h, P2_1);
            }

            float a, b;
            upk(P1_0, a, b); const float i1 = sig_h(a), f1 = sig_h(b);
            upk(P1_1, a, b); const float g1 = tanhap(a), o1 = sig_h(b);
            upk(P2_0, a, b); const float i2 = sig_h(a), f2 = sig_h(b);
            upk(P2_1, a, b); const float g2 = tanhap(a), o2 = sig_h(b);

            c1 = fmaf(f1, c1, i1 * g1);
            c2 = fmaf(f2, c2, i2 * g2);
            const float h1o = o1 * tanhap(c1);
            const float h2o = o2 * tanhap(c2);

            #pragma unroll
            for (int k = 0; k < H; k++) {
                const float v1 = __shfl_sync(0xffffffffu, h1o, k, 8);
                const float v2 = __shfl_sync(0xffffffffu, h2o, k, 8);
                h1p[k] = pk2(v1, v1);
                h2p[k] = pk2(v2, v2);
            }
        }
        xv = xn;
    }
    // loop produced h2 = h2(T-1); the final (extra) L1 result is unused.

    // ---- FC head: out[e][j] = b_fc[j] + sum_k Wfc[j][k]*h2[k], j < 4 ----
    if (j < 4) {
        float acc = bfc[j];
        #pragma unroll
        for (int k = 0; k < H; k++) {
            float lo, hi;
            upk(h2p[k], lo, hi);
            acc = fmaf(Wfc[j * H + k], lo, acc);
        }
        out[e * 4 + j] = acc;
    }
}

extern "C" void kernel_launch(void* const* d_in, const int* in_sizes, int n_in,
                              void* d_out, int out_size)
{
    const float* x    = (const float*)d_in[0];
    const float* Wih1 = (const float*)d_in[1];
    const float* Whh1 = (const float*)d_in[2];
    const float* bih1 = (const float*)d_in[3];
    const float* bhh1 = (const float*)d_in[4];
    const float* Wih2 = (const float*)d_in[5];
    const float* Whh2 = (const float*)d_in[6];
    const float* bih2 = (const float*)d_in[7];
    const float* bhh2 = (const float*)d_in[8];
    const float* Wfc  = (const float*)d_in[9];
    const float* bfc  = (const float*)d_in[10];
    float* out = (float*)d_out;

    const int B = 4096;
    dim3 grid(B * 8 / 32), block(32);
    lstm2_kernel<<<grid, block>>>(x, Wih1, Whh1, bih1, bhh1,
                                  Wih2, Whh2, bih2, bhh2, Wfc, bfc, out);
}